// round 3
// baseline (speedup 1.0000x reference)
#include <cuda_runtime.h>
#include <math.h>
#include <stdint.h>

#define NN 32768          // nodes
#define NE 524288         // edges
#define DD 128
#define NB 512            // graphs
#define HID 256

// ---------------- scratch (device globals; no allocation allowed) ----------
__device__ __align__(16) float g_x[NN * DD];
__device__ __align__(16) float g_agg[NN * DD];
__device__ __align__(16) float g_t[NN * HID];
__device__ __align__(16) float g_h[NN * DD];
__device__ float g_gate[NN];
__device__ __align__(16) float g_pool[NB * DD];
__device__ int g_counts[NN];
__device__ int g_off[NN + 1];
__device__ int g_cursor[NN];
__device__ int g_psrc[NE];
__device__ int g_pattr[NE];

// ---------------- helpers ----------------
__device__ __forceinline__ float gelu_erf(float x) {
    return 0.5f * x * (1.0f + erff(x * 0.70710678118654752f));
}
__device__ __forceinline__ uint32_t f2tf32(float x) {
    uint32_t r;
    asm("cvt.rna.tf32.f32 %0, %1;" : "=r"(r) : "f"(x));
    return r;
}

// ---------------- build x = logits[masked] + atom_emb[feat] ----------------
__global__ void k_build_x(const float* __restrict__ logits,
                          const int* __restrict__ af,
                          const float* __restrict__ aemb) {
    int node = blockIdx.x;
    int d = threadIdx.x;
    int b = node >> 6, a = node & 63;
    g_x[node * DD + d] = logits[b * (128 * DD) + a * DD + d] + aemb[af[node] * DD + d];
}

// ---------------- CSR build ----------------
__global__ void k_zero_counts() {
    int i = blockIdx.x * blockDim.x + threadIdx.x;
    if (i < NN) g_counts[i] = 0;
}
__global__ void k_hist(const int* __restrict__ dst) {
    int e = blockIdx.x * blockDim.x + threadIdx.x;
    if (e < NE) atomicAdd(&g_counts[dst[e]], 1);
}
__global__ void k_scan() {
    __shared__ int part[1024];
    int tid = threadIdx.x;
    int base = tid * 32;
    int local[32];
    int s = 0;
#pragma unroll
    for (int i = 0; i < 32; i++) { local[i] = s; s += g_counts[base + i]; }
    part[tid] = s;
    __syncthreads();
    for (int ofs = 1; ofs < 1024; ofs <<= 1) {
        int v = 0;
        if (tid >= ofs) v = part[tid - ofs];
        __syncthreads();
        part[tid] += v;
        __syncthreads();
    }
    int prefix = (tid == 0) ? 0 : part[tid - 1];
#pragma unroll
    for (int i = 0; i < 32; i++) {
        int o = prefix + local[i];
        g_off[base + i] = o;
        g_cursor[base + i] = o;
    }
    if (tid == 1023) g_off[NN] = part[1023];
}
__global__ void k_scatter(const int* __restrict__ src,
                          const int* __restrict__ dst,
                          const int* __restrict__ attr) {
    int e = blockIdx.x * blockDim.x + threadIdx.x;
    if (e < NE) {
        int p = atomicAdd(&g_cursor[dst[e]], 1);
        g_psrc[p] = src[e];
        g_pattr[p] = attr[e];
    }
}

// ---------------- edge aggregation: agg[i] = sum relu(x[src]+eemb[attr]) ---
__global__ __launch_bounds__(256) void k_aggregate(const float* __restrict__ eemb_g) {
    __shared__ float eemb[8 * DD];
    for (int i = threadIdx.x; i < 8 * DD; i += 256) eemb[i] = eemb_g[i];
    __syncthreads();
    int warp = (blockIdx.x * 256 + threadIdx.x) >> 5;
    int lane = threadIdx.x & 31;
    int s = g_off[warp], e = g_off[warp + 1];
    float4 acc = make_float4(0.f, 0.f, 0.f, 0.f);
    for (int j = s; j < e; j++) {
        int sn = g_psrc[j];
        int ea = g_pattr[j];
        float4 xv = *(const float4*)&g_x[sn * DD + lane * 4];
        const float* em = &eemb[ea * DD + lane * 4];
        acc.x += fmaxf(xv.x + em[0], 0.f);
        acc.y += fmaxf(xv.y + em[1], 0.f);
        acc.z += fmaxf(xv.z + em[2], 0.f);
        acc.w += fmaxf(xv.w + em[3], 0.f);
    }
    *(float4*)&g_agg[warp * DD + lane * 4] = acc;
}

// ---------------- TF32 tensor-core GEMM ------------------------------------
// C[M,N] = act(A[M,K] @ W[K,N] + bias), A,W,C row-major fp32 (tf32-rounded).
// CTA tile 128x64, BK=32, 256 threads = 8 warps in 4(M) x 2(N) grid,
// warp tile 32x32 via mma.sync.m16n8k8 (2 mi x 4 ni fragments).
#define AS_STRIDE 36
#define WS_STRIDE 72
__global__ __launch_bounds__(256) void k_mma_gemm(const float* __restrict__ A,
                                                  const float* __restrict__ W,
                                                  const float* __restrict__ bias,
                                                  float* __restrict__ C,
                                                  int K, int N, int relu) {
    __shared__ __align__(16) uint32_t As[128 * AS_STRIDE];
    __shared__ __align__(16) uint32_t Ws[32 * WS_STRIDE];
    int tid = threadIdx.x;
    int lane = tid & 31;
    int wid = tid >> 5;
    int warp_m = (wid >> 1) * 32;      // 0,32,64,96
    int warp_n = (wid & 1) * 32;       // 0,32
    int m0 = blockIdx.x * 128;
    int n0 = blockIdx.y * 64;

    float acc[2][4][4];
#pragma unroll
    for (int i = 0; i < 2; i++)
#pragma unroll
        for (int j = 0; j < 4; j++)
#pragma unroll
            for (int c = 0; c < 4; c++) acc[i][j][c] = 0.f;

    int gid = lane >> 2;   // 0..7
    int tig = lane & 3;    // 0..3

    for (int k0 = 0; k0 < K; k0 += 32) {
        // load A tile 128x32 -> As (tf32-rounded)
        {
            int r = tid >> 3;            // 0..31
            int c4 = (tid & 7) * 4;      // 0..28
#pragma unroll
            for (int p = 0; p < 4; p++) {
                int row = r + p * 32;
                float4 v = *(const float4*)&A[(size_t)(m0 + row) * K + k0 + c4];
                uint32_t* d = &As[row * AS_STRIDE + c4];
                d[0] = f2tf32(v.x); d[1] = f2tf32(v.y);
                d[2] = f2tf32(v.z); d[3] = f2tf32(v.w);
            }
        }
        // load W tile 32x64 -> Ws (tf32-rounded)
        {
            int r = tid >> 4;            // 0..15
            int c4 = (tid & 15) * 4;     // 0..60
#pragma unroll
            for (int p = 0; p < 2; p++) {
                int row = r + p * 16;
                float4 v = *(const float4*)&W[(size_t)(k0 + row) * N + n0 + c4];
                uint32_t* d = &Ws[row * WS_STRIDE + c4];
                d[0] = f2tf32(v.x); d[1] = f2tf32(v.y);
                d[2] = f2tf32(v.z); d[3] = f2tf32(v.w);
            }
        }
        __syncthreads();
#pragma unroll
        for (int kk = 0; kk < 32; kk += 8) {
            uint32_t af[2][4];
#pragma unroll
            for (int mi = 0; mi < 2; mi++) {
                int mb = warp_m + mi * 16;
                af[mi][0] = As[(mb + gid) * AS_STRIDE + kk + tig];
                af[mi][1] = As[(mb + gid + 8) * AS_STRIDE + kk + tig];
                af[mi][2] = As[(mb + gid) * AS_STRIDE + kk + tig + 4];
                af[mi][3] = As[(mb + gid + 8) * AS_STRIDE + kk + tig + 4];
            }
            uint32_t bf[4][2];
#pragma unroll
            for (int ni = 0; ni < 4; ni++) {
                int nb = warp_n + ni * 8;
                bf[ni][0] = Ws[(kk + tig) * WS_STRIDE + nb + gid];
                bf[ni][1] = Ws[(kk + tig + 4) * WS_STRIDE + nb + gid];
            }
#pragma unroll
            for (int mi = 0; mi < 2; mi++)
#pragma unroll
                for (int ni = 0; ni < 4; ni++) {
                    asm volatile(
                        "mma.sync.aligned.m16n8k8.row.col.f32.tf32.tf32.f32 "
                        "{%0,%1,%2,%3}, {%4,%5,%6,%7}, {%8,%9}, {%0,%1,%2,%3};"
                        : "+f"(acc[mi][ni][0]), "+f"(acc[mi][ni][1]),
                          "+f"(acc[mi][ni][2]), "+f"(acc[mi][ni][3])
                        : "r"(af[mi][0]), "r"(af[mi][1]),
                          "r"(af[mi][2]), "r"(af[mi][3]),
                          "r"(bf[ni][0]), "r"(bf[ni][1]));
                }
        }
        __syncthreads();
    }
    // epilogue
#pragma unroll
    for (int mi = 0; mi < 2; mi++) {
        int row0 = m0 + warp_m + mi * 16 + gid;
#pragma unroll
        for (int ni = 0; ni < 4; ni++) {
            int col = n0 + warp_n + ni * 8 + tig * 2;
            float b0 = bias[col], b1 = bias[col + 1];
            float2 o0 = make_float2(acc[mi][ni][0] + b0, acc[mi][ni][1] + b1);
            float2 o1 = make_float2(acc[mi][ni][2] + b0, acc[mi][ni][3] + b1);
            if (relu) {
                o0.x = fmaxf(o0.x, 0.f); o0.y = fmaxf(o0.y, 0.f);
                o1.x = fmaxf(o1.x, 0.f); o1.y = fmaxf(o1.y, 0.f);
            }
            *(float2*)&C[(size_t)row0 * N + col] = o0;
            *(float2*)&C[(size_t)(row0 + 8) * N + col] = o1;
        }
    }
}

// ---------------- x += LN(h) (per row, warp) ----------------
__global__ __launch_bounds__(256) void k_ln_residual(const float* __restrict__ h,
                                                     const float* __restrict__ gam,
                                                     const float* __restrict__ bet) {
    int row = (blockIdx.x * 256 + threadIdx.x) >> 5;
    int lane = threadIdx.x & 31;
    float4 v = *(const float4*)&h[row * DD + lane * 4];
    float s = v.x + v.y + v.z + v.w;
#pragma unroll
    for (int o = 16; o; o >>= 1) s += __shfl_xor_sync(0xffffffffu, s, o);
    float mu = s * (1.f / 128.f);
    float dx = v.x - mu, dy = v.y - mu, dz = v.z - mu, dw = v.w - mu;
    float q = dx * dx + dy * dy + dz * dz + dw * dw;
#pragma unroll
    for (int o = 16; o; o >>= 1) q += __shfl_xor_sync(0xffffffffu, q, o);
    float rs = rsqrtf(q * (1.f / 128.f) + 1e-5f);
    float4 g4 = *(const float4*)&gam[lane * 4];
    float4 b4 = *(const float4*)&bet[lane * 4];
    float4 xo = *(const float4*)&g_x[row * DD + lane * 4];
    xo.x += dx * rs * g4.x + b4.x;
    xo.y += dy * rs * g4.y + b4.y;
    xo.z += dz * rs * g4.z + b4.z;
    xo.w += dw * rs * g4.w + b4.w;
    *(float4*)&g_x[row * DD + lane * 4] = xo;
}

// ---------------- gate = relu(LN256(t)) . W2 + b2 (per row, warp) ----------
__global__ __launch_bounds__(256) void k_gate_finish(const float* __restrict__ gam,
                                                     const float* __restrict__ bet,
                                                     const float* __restrict__ w2,
                                                     const float* __restrict__ b2) {
    int row = (blockIdx.x * 256 + threadIdx.x) >> 5;
    int lane = threadIdx.x & 31;
    float4 v0 = *(const float4*)&g_t[row * HID + lane * 4];
    float4 v1 = *(const float4*)&g_t[row * HID + 128 + lane * 4];
    float s = v0.x + v0.y + v0.z + v0.w + v1.x + v1.y + v1.z + v1.w;
#pragma unroll
    for (int o = 16; o; o >>= 1) s += __shfl_xor_sync(0xffffffffu, s, o);
    float mu = s * (1.f / 256.f);
    float d0x = v0.x - mu, d0y = v0.y - mu, d0z = v0.z - mu, d0w = v0.w - mu;
    float d1x = v1.x - mu, d1y = v1.y - mu, d1z = v1.z - mu, d1w = v1.w - mu;
    float q = d0x * d0x + d0y * d0y + d0z * d0z + d0w * d0w +
              d1x * d1x + d1y * d1y + d1z * d1z + d1w * d1w;
#pragma unroll
    for (int o = 16; o; o >>= 1) q += __shfl_xor_sync(0xffffffffu, q, o);
    float rs = rsqrtf(q * (1.f / 256.f) + 1e-5f);
    float4 ga = *(const float4*)&gam[lane * 4];
    float4 gb = *(const float4*)&bet[lane * 4];
    float4 ga1 = *(const float4*)&gam[128 + lane * 4];
    float4 gb1 = *(const float4*)&bet[128 + lane * 4];
    float4 wa = *(const float4*)&w2[lane * 4];
    float4 wb = *(const float4*)&w2[128 + lane * 4];
    float dot =
        fmaxf(d0x * rs * ga.x + gb.x, 0.f) * wa.x +
        fmaxf(d0y * rs * ga.y + gb.y, 0.f) * wa.y +
        fmaxf(d0z * rs * ga.z + gb.z, 0.f) * wa.z +
        fmaxf(d0w * rs * ga.w + gb.w, 0.f) * wa.w +
        fmaxf(d1x * rs * ga1.x + gb1.x, 0.f) * wb.x +
        fmaxf(d1y * rs * ga1.y + gb1.y, 0.f) * wb.y +
        fmaxf(d1z * rs * ga1.z + gb1.z, 0.f) * wb.z +
        fmaxf(d1w * rs * ga1.w + gb1.w, 0.f) * wb.w;
#pragma unroll
    for (int o = 16; o; o >>= 1) dot += __shfl_xor_sync(0xffffffffu, dot, o);
    if (lane == 0) g_gate[row] = dot + b2[0];
}

// ---------------- segment softmax + weighted pool (block per graph) --------
__global__ __launch_bounds__(128) void k_pool() {
    __shared__ float w[64];
    int b = blockIdx.x;
    int tid = threadIdx.x;
    if (tid < 32) {
        float g0 = g_gate[b * 64 + tid];
        float g1 = g_gate[b * 64 + 32 + tid];
        float m = fmaxf(g0, g1);
#pragma unroll
        for (int o = 16; o; o >>= 1) m = fmaxf(m, __shfl_xor_sync(0xffffffffu, m, o));
        float e0 = expf(g0 - m), e1 = expf(g1 - m);
        float s = e0 + e1;
#pragma unroll
        for (int o = 16; o; o >>= 1) s += __shfl_xor_sync(0xffffffffu, s, o);
        w[tid] = e0 / s;
        w[tid + 32] = e1 / s;
    }
    __syncthreads();
    float acc = 0.f;
#pragma unroll 8
    for (int i = 0; i < 64; i++) acc += w[i] * g_x[(b * 64 + i) * DD + tid];
    g_pool[b * DD + tid] = acc;
}

// ---------------- tail: 2 residual blocks + head (block per graph) ---------
__device__ __forceinline__ float block_ln(float v, float g, float bt, float* red) {
    int lane = threadIdx.x & 31, wid = threadIdx.x >> 5;
    float s = v;
#pragma unroll
    for (int o = 16; o; o >>= 1) s += __shfl_xor_sync(0xffffffffu, s, o);
    if (lane == 0) red[wid] = s;
    __syncthreads();
    float mu = (red[0] + red[1] + red[2] + red[3]) * (1.f / 128.f);
    float d = v - mu;
    float q = d * d;
#pragma unroll
    for (int o = 16; o; o >>= 1) q += __shfl_xor_sync(0xffffffffu, q, o);
    if (lane == 0) red[4 + wid] = q;
    __syncthreads();
    float var = (red[4] + red[5] + red[6] + red[7]) * (1.f / 128.f);
    float out = d * rsqrtf(var + 1e-5f) * g + bt;
    __syncthreads();
    return out;
}

__global__ __launch_bounds__(128) void k_tail(
    const float* __restrict__ fc1W, const float* __restrict__ fc1b,
    const float* __restrict__ ln1g, const float* __restrict__ ln1b,
    const float* __restrict__ fc2W, const float* __restrict__ fc2b,
    const float* __restrict__ ln2g, const float* __restrict__ ln2b,
    const float* __restrict__ pW1, const float* __restrict__ pb1,
    const float* __restrict__ pW2, const float* __restrict__ pb2,
    float* __restrict__ out) {
    __shared__ float sg[128], sh[128], red[8];
    int b = blockIdx.x, n = threadIdx.x;
    sg[n] = g_pool[b * DD + n];
    __syncthreads();
#pragma unroll
    for (int r = 0; r < 2; r++) {
        const float* W1 = fc1W + r * DD * DD;
        const float* W2 = fc2W + r * DD * DD;
        float u = fc1b[r * DD + n];
#pragma unroll 16
        for (int k = 0; k < 128; k++) u += sg[k] * W1[k * DD + n];
        float hn = gelu_erf(block_ln(u, ln1g[r * DD + n], ln1b[r * DD + n], red));
        sh[n] = hn;
        __syncthreads();
        float v2 = fc2b[r * DD + n];
#pragma unroll 16
        for (int k = 0; k < 128; k++) v2 += sh[k] * W2[k * DD + n];
        float h2 = block_ln(v2, ln2g[r * DD + n], ln2b[r * DD + n], red);
        sg[n] += h2;
        __syncthreads();
    }
    float u = pb1[n];
#pragma unroll 16
    for (int k = 0; k < 128; k++) u += sg[k] * pW1[k * DD + n];
    sh[n] = gelu_erf(u);
    __syncthreads();
    if (n < 12) {
        float o = pb2[n];
#pragma unroll 16
        for (int k = 0; k < 128; k++) o += sh[k] * pW2[k * 12 + n];
        out[b * 12 + n] = o;
    }
}

// ---------------- launch ----------------
extern "C" void kernel_launch(void* const* d_in, const int* in_sizes, int n_in,
                              void* d_out, int out_size) {
    const float* logits   = (const float*)d_in[0];
    // d_in[1] atom_mask: statically known, unused
    const int*   atom_feature = (const int*)d_in[2];
    const int*   edge_index   = (const int*)d_in[3];
    const int*   edge_attr    = (const int*)d_in[4];
    // d_in[5] batch_idx: statically known, unused
    const float* atom_emb = (const float*)d_in[6];
    const float* edge_emb = (const float*)d_in[7];
    const float* gnn_W1 = (const float*)d_in[8];
    const float* gnn_b1 = (const float*)d_in[9];
    const float* gnn_W2 = (const float*)d_in[10];
    const float* gnn_b2 = (const float*)d_in[11];
    const float* gnn_ln_g = (const float*)d_in[12];
    const float* gnn_ln_b = (const float*)d_in[13];
    const float* gate_W1 = (const float*)d_in[14];
    const float* gate_b1 = (const float*)d_in[15];
    const float* gate_ln_g = (const float*)d_in[16];
    const float* gate_ln_b = (const float*)d_in[17];
    const float* gate_W2 = (const float*)d_in[18];
    const float* gate_b2 = (const float*)d_in[19];
    const float* res_fc1_W = (const float*)d_in[20];
    const float* res_fc1_b = (const float*)d_in[21];
    const float* res_ln1_g = (const float*)d_in[22];
    const float* res_ln1_b = (const float*)d_in[23];
    const float* res_fc2_W = (const float*)d_in[24];
    const float* res_fc2_b = (const float*)d_in[25];
    const float* res_ln2_g = (const float*)d_in[26];
    const float* res_ln2_b = (const float*)d_in[27];
    const float* pred_W1 = (const float*)d_in[28];
    const float* pred_b1 = (const float*)d_in[29];
    const float* pred_W2 = (const float*)d_in[30];
    const float* pred_b2 = (const float*)d_in[31];
    float* out = (float*)d_out;

    const int* e_src = edge_index;
    const int* e_dst = edge_index + NE;

    float *xp, *aggp, *tp, *hp;
    cudaGetSymbolAddress((void**)&xp, g_x);
    cudaGetSymbolAddress((void**)&aggp, g_agg);
    cudaGetSymbolAddress((void**)&tp, g_t);
    cudaGetSymbolAddress((void**)&hp, g_h);

    k_build_x<<<NN, 128>>>(logits, atom_feature, atom_emb);
    k_zero_counts<<<NN / 256, 256>>>();
    k_hist<<<NE / 256, 256>>>(e_dst);
    k_scan<<<1, 1024>>>();
    k_scatter<<<NE / 256, 256>>>(e_src, e_dst, edge_attr);

    for (int l = 0; l < 3; l++) {
        k_aggregate<<<NN / 8, 256>>>(edge_emb);
        k_mma_gemm<<<dim3(NN / 128, HID / 64), 256>>>(aggp, gnn_W1 + l * DD * HID,
                                                      gnn_b1 + l * HID, tp, DD, HID, 1);
        k_mma_gemm<<<dim3(NN / 128, DD / 64), 256>>>(tp, gnn_W2 + l * HID * DD,
                                                     gnn_b2 + l * DD, hp, HID, DD, 0);
        k_ln_residual<<<NN / 8, 256>>>(hp, gnn_ln_g + l * DD, gnn_ln_b + l * DD);
    }

    k_mma_gemm<<<dim3(NN / 128, HID / 64), 256>>>(xp, gate_W1, gate_b1, tp, DD, HID, 0);
    k_gate_finish<<<NN / 8, 256>>>(gate_ln_g, gate_ln_b, gate_W2, gate_b2);
    k_pool<<<NB, 128>>>();
    k_tail<<<NB, 128>>>(res_fc1_W, res_fc1_b, res_ln1_g, res_ln1_b,
                        res_fc2_W, res_fc2_b, res_ln2_g, res_ln2_b,
                        pred_W1, pred_b1, pred_W2, pred_b2, out);
}

// round 6
// speedup vs baseline: 1.1563x; 1.1563x over previous
#include <cuda_runtime.h>
#include <cuda_fp16.h>
#include <math.h>
#include <stdint.h>

#define NN 32768          // nodes
#define NE 524288         // edges
#define DD 128
#define NB 512            // graphs
#define HID 256

// ---------------- scratch (device globals; no allocation allowed) ----------
__device__ __align__(16) float g_x[NN * DD];
__device__ __align__(16) __half g_xh[NN * DD];   // fp16 mirror of x for gathers
__device__ __align__(16) float g_agg[NN * DD];
__device__ __align__(16) float g_t[NN * HID];
__device__ __align__(16) float g_h[NN * DD];
__device__ float g_gate[NN];
__device__ __align__(16) float g_pool[NB * DD];
__device__ int g_counts[NN];
__device__ int g_off[NN + 1];
__device__ int g_cursor[NN];
__device__ int g_bsum[32];
__device__ int g_boff[32];
__device__ int g_pe[NE];        // packed (src<<3)|attr

// ---------------- helpers ----------------
__device__ __forceinline__ float gelu_erf(float x) {
    return 0.5f * x * (1.0f + erff(x * 0.70710678118654752f));
}
__device__ __forceinline__ uint32_t f2tf32(float x) {
    uint32_t r;
    asm("cvt.rna.tf32.f32 %0, %1;" : "=r"(r) : "f"(x));
    return r;
}

// ---------------- build x = logits[masked] + atom_emb[feat] ----------------
__global__ void k_build_x(const float* __restrict__ logits,
                          const int* __restrict__ af,
                          const float* __restrict__ aemb) {
    int node = blockIdx.x;
    int d = threadIdx.x;          // 128 threads, 1 dim each
    int b = node >> 6, a = node & 63;
    float v = logits[b * (128 * DD) + a * DD + d] + aemb[af[node] * DD + d];
    g_x[node * DD + d] = v;
    g_xh[node * DD + d] = __float2half(v);
}

// ---------------- CSR build ----------------
__global__ void k_zero_counts() {
    int i = blockIdx.x * blockDim.x + threadIdx.x;
    if (i < NN) g_counts[i] = 0;
}
__global__ void k_hist(const int* __restrict__ dst) {
    int e = blockIdx.x * blockDim.x + threadIdx.x;
    atomicAdd(&g_counts[dst[e]], 1);
    atomicAdd(&g_counts[dst[e + NE / 2]], 1);
}
// hierarchical scan: 32 blocks x 1024, then 32-wide, then add offsets
__global__ __launch_bounds__(1024) void k_scan1() {
    __shared__ int sh[1024];
    int b = blockIdx.x, t = threadIdx.x, i = b * 1024 + t;
    int v = g_counts[i];
    sh[t] = v;
    __syncthreads();
    for (int o = 1; o < 1024; o <<= 1) {
        int u = 0;
        if (t >= o) u = sh[t - o];
        __syncthreads();
        sh[t] += u;
        __syncthreads();
    }
    g_off[i] = sh[t] - v;     // exclusive
    if (t == 1023) g_bsum[b] = sh[1023];
}
__global__ void k_scan2() {
    int t = threadIdx.x;      // 32 threads
    int v = g_bsum[t];
    int s = v;
#pragma unroll
    for (int o = 1; o < 32; o <<= 1) {
        int u = __shfl_up_sync(0xffffffffu, s, o);
        if (t >= o) s += u;
    }
    g_boff[t] = s - v;
}
__global__ __launch_bounds__(1024) void k_scan3() {
    int b = blockIdx.x, t = threadIdx.x, i = b * 1024 + t;
    int o = g_off[i] + g_boff[b];
    g_off[i] = o;
    g_cursor[i] = o;
    if (i == 0) g_off[NN] = NE;
}
__global__ void k_scatter(const int* __restrict__ src,
                          const int* __restrict__ dst,
                          const int* __restrict__ attr) {
    int e = blockIdx.x * blockDim.x + threadIdx.x;
#pragma unroll
    for (int h = 0; h < 2; h++) {
        int ee = e + h * (NE / 2);
        int p = atomicAdd(&g_cursor[dst[ee]], 1);
        g_pe[p] = (src[ee] << 3) | attr[ee];
    }
}

// ---------------- edge aggregation: agg[i] = sum relu(x[src]+eemb[attr]) ---
// warp per node; x gathered in fp16 (256B/row), eemb fp32 in smem
__global__ __launch_bounds__(256) void k_aggregate(const float* __restrict__ eemb_g) {
    __shared__ float eemb[8 * DD];
    for (int i = threadIdx.x; i < 8 * DD; i += 256) eemb[i] = eemb_g[i];
    __syncthreads();
    int warp = (blockIdx.x * 256 + threadIdx.x) >> 5;
    int lane = threadIdx.x & 31;
    int s = g_off[warp], e = g_off[warp + 1];
    float4 acc = make_float4(0.f, 0.f, 0.f, 0.f);
    const float* emb = &eemb[(lane * 4)];
    for (int j = s; j < e; j++) {
        int p = g_pe[j];
        int sn = p >> 3;
        const float* em = emb + (p & 7) * DD;
        uint2 hv = *(const uint2*)&g_xh[sn * DD + lane * 4];
        float2 f0 = __half22float2(*(const __half2*)&hv.x);
        float2 f1 = __half22float2(*(const __half2*)&hv.y);
        acc.x += fmaxf(f0.x + em[0], 0.f);
        acc.y += fmaxf(f0.y + em[1], 0.f);
        acc.z += fmaxf(f1.x + em[2], 0.f);
        acc.w += fmaxf(f1.y + em[3], 0.f);
    }
    *(float4*)&g_agg[warp * DD + lane * 4] = acc;
}

// ---------------- TF32 tensor-core GEMM ------------------------------------
// C[M,N] = act(A[M,K] @ W[K,N] + bias), CTA tile 128x64, BK=32,
// 256 threads = 8 warps (4M x 2N), warp tile 32x32 via mma.m16n8k8.
#define AS_STRIDE 36
#define WS_STRIDE 72
__global__ __launch_bounds__(256) void k_mma_gemm(const float* __restrict__ A,
                                                  const float* __restrict__ W,
                                                  const float* __restrict__ bias,
                                                  float* __restrict__ C,
                                                  int K, int N, int relu) {
    __shared__ __align__(16) uint32_t As[128 * AS_STRIDE];
    __shared__ __align__(16) uint32_t Ws[32 * WS_STRIDE];
    int tid = threadIdx.x;
    int lane = tid & 31;
    int wid = tid >> 5;
    int warp_m = (wid >> 1) * 32;
    int warp_n = (wid & 1) * 32;
    int m0 = blockIdx.x * 128;
    int n0 = blockIdx.y * 64;

    float acc[2][4][4];
#pragma unroll
    for (int i = 0; i < 2; i++)
#pragma unroll
        for (int j = 0; j < 4; j++)
#pragma unroll
            for (int c = 0; c < 4; c++) acc[i][j][c] = 0.f;

    int gid = lane >> 2;
    int tig = lane & 3;

    for (int k0 = 0; k0 < K; k0 += 32) {
        {
            int r = tid >> 3;
            int c4 = (tid & 7) * 4;
#pragma unroll
            for (int p = 0; p < 4; p++) {
                int row = r + p * 32;
                float4 v = *(const float4*)&A[(size_t)(m0 + row) * K + k0 + c4];
                uint32_t* d = &As[row * AS_STRIDE + c4];
                d[0] = f2tf32(v.x); d[1] = f2tf32(v.y);
                d[2] = f2tf32(v.z); d[3] = f2tf32(v.w);
            }
        }
        {
            int r = tid >> 4;
            int c4 = (tid & 15) * 4;
#pragma unroll
            for (int p = 0; p < 2; p++) {
                int row = r + p * 16;
                float4 v = *(const float4*)&W[(size_t)(k0 + row) * N + n0 + c4];
                uint32_t* d = &Ws[row * WS_STRIDE + c4];
                d[0] = f2tf32(v.x); d[1] = f2tf32(v.y);
                d[2] = f2tf32(v.z); d[3] = f2tf32(v.w);
            }
        }
        __syncthreads();
#pragma unroll
        for (int kk = 0; kk < 32; kk += 8) {
            uint32_t af[2][4];
#pragma unroll
            for (int mi = 0; mi < 2; mi++) {
                int mb = warp_m + mi * 16;
                af[mi][0] = As[(mb + gid) * AS_STRIDE + kk + tig];
                af[mi][1] = As[(mb + gid + 8) * AS_STRIDE + kk + tig];
                af[mi][2] = As[(mb + gid) * AS_STRIDE + kk + tig + 4];
                af[mi][3] = As[(mb + gid + 8) * AS_STRIDE + kk + tig + 4];
            }
            uint32_t bf[4][2];
#pragma unroll
            for (int ni = 0; ni < 4; ni++) {
                int nb = warp_n + ni * 8;
                bf[ni][0] = Ws[(kk + tig) * WS_STRIDE + nb + gid];
                bf[ni][1] = Ws[(kk + tig + 4) * WS_STRIDE + nb + gid];
            }
#pragma unroll
            for (int mi = 0; mi < 2; mi++)
#pragma unroll
                for (int ni = 0; ni < 4; ni++) {
                    asm volatile(
                        "mma.sync.aligned.m16n8k8.row.col.f32.tf32.tf32.f32 "
                        "{%0,%1,%2,%3}, {%4,%5,%6,%7}, {%8,%9}, {%0,%1,%2,%3};"
                        : "+f"(acc[mi][ni][0]), "+f"(acc[mi][ni][1]),
                          "+f"(acc[mi][ni][2]), "+f"(acc[mi][ni][3])
                        : "r"(af[mi][0]), "r"(af[mi][1]),
                          "r"(af[mi][2]), "r"(af[mi][3]),
                          "r"(bf[ni][0]), "r"(bf[ni][1]));
                }
        }
        __syncthreads();
    }
#pragma unroll
    for (int mi = 0; mi < 2; mi++) {
        int row0 = m0 + warp_m + mi * 16 + gid;
#pragma unroll
        for (int ni = 0; ni < 4; ni++) {
            int col = n0 + warp_n + ni * 8 + tig * 2;
            float b0 = bias[col], b1 = bias[col + 1];
            float2 o0 = make_float2(acc[mi][ni][0] + b0, acc[mi][ni][1] + b1);
            float2 o1 = make_float2(acc[mi][ni][2] + b0, acc[mi][ni][3] + b1);
            if (relu) {
                o0.x = fmaxf(o0.x, 0.f); o0.y = fmaxf(o0.y, 0.f);
                o1.x = fmaxf(o1.x, 0.f); o1.y = fmaxf(o1.y, 0.f);
            }
            *(float2*)&C[(size_t)row0 * N + col] = o0;
            *(float2*)&C[(size_t)(row0 + 8) * N + col] = o1;
        }
    }
}

// ---------------- x += LN(h); refresh fp16 mirror (per row, warp) ----------
__global__ __launch_bounds__(256) void k_ln_residual(const float* __restrict__ h,
                                                     const float* __restrict__ gam,
                                                     const float* __restrict__ bet) {
    int row = (blockIdx.x * 256 + threadIdx.x) >> 5;
    int lane = threadIdx.x & 31;
    float4 v = *(const float4*)&h[row * DD + lane * 4];
    float s = v.x + v.y + v.z + v.w;
#pragma unroll
    for (int o = 16; o; o >>= 1) s += __shfl_xor_sync(0xffffffffu, s, o);
    float mu = s * (1.f / 128.f);
    float dx = v.x - mu, dy = v.y - mu, dz = v.z - mu, dw = v.w - mu;
    float q = dx * dx + dy * dy + dz * dz + dw * dw;
#pragma unroll
    for (int o = 16; o; o >>= 1) q += __shfl_xor_sync(0xffffffffu, q, o);
    float rs = rsqrtf(q * (1.f / 128.f) + 1e-5f);
    float4 g4 = *(const float4*)&gam[lane * 4];
    float4 b4 = *(const float4*)&bet[lane * 4];
    float4 xo = *(const float4*)&g_x[row * DD + lane * 4];
    xo.x += dx * rs * g4.x + b4.x;
    xo.y += dy * rs * g4.y + b4.y;
    xo.z += dz * rs * g4.z + b4.z;
    xo.w += dw * rs * g4.w + b4.w;
    *(float4*)&g_x[row * DD + lane * 4] = xo;
    __half2 h0 = __floats2half2_rn(xo.x, xo.y);
    __half2 h1 = __floats2half2_rn(xo.z, xo.w);
    uint2 hv;
    hv.x = *(uint32_t*)&h0;
    hv.y = *(uint32_t*)&h1;
    *(uint2*)&g_xh[row * DD + lane * 4] = hv;
}

// ---------------- gate = relu(LN256(t)) . W2 + b2 (per row, warp) ----------
__global__ __launch_bounds__(256) void k_gate_finish(const float* __restrict__ gam,
                                                     const float* __restrict__ bet,
                                                     const float* __restrict__ w2,
                                                     const float* __restrict__ b2) {
    int row = (blockIdx.x * 256 + threadIdx.x) >> 5;
    int lane = threadIdx.x & 31;
    float4 v0 = *(const float4*)&g_t[row * HID + lane * 4];
    float4 v1 = *(const float4*)&g_t[row * HID + 128 + lane * 4];
    float s = v0.x + v0.y + v0.z + v0.w + v1.x + v1.y + v1.z + v1.w;
#pragma unroll
    for (int o = 16; o; o >>= 1) s += __shfl_xor_sync(0xffffffffu, s, o);
    float mu = s * (1.f / 256.f);
    float d0x = v0.x - mu, d0y = v0.y - mu, d0z = v0.z - mu, d0w = v0.w - mu;
    float d1x = v1.x - mu, d1y = v1.y - mu, d1z = v1.z - mu, d1w = v1.w - mu;
    float q = d0x * d0x + d0y * d0y + d0z * d0z + d0w * d0w +
              d1x * d1x + d1y * d1y + d1z * d1z + d1w * d1w;
#pragma unroll
    for (int o = 16; o; o >>= 1) q += __shfl_xor_sync(0xffffffffu, q, o);
    float rs = rsqrtf(q * (1.f / 256.f) + 1e-5f);
    float4 ga = *(const float4*)&gam[lane * 4];
    float4 gb = *(const float4*)&bet[lane * 4];
    float4 ga1 = *(const float4*)&gam[128 + lane * 4];
    float4 gb1 = *(const float4*)&bet[128 + lane * 4];
    float4 wa = *(const float4*)&w2[lane * 4];
    float4 wb = *(const float4*)&w2[128 + lane * 4];
    float dot =
        fmaxf(d0x * rs * ga.x + gb.x, 0.f) * wa.x +
        fmaxf(d0y * rs * ga.y + gb.y, 0.f) * wa.y +
        fmaxf(d0z * rs * ga.z + gb.z, 0.f) * wa.z +
        fmaxf(d0w * rs * ga.w + gb.w, 0.f) * wa.w +
        fmaxf(d1x * rs * ga1.x + gb1.x, 0.f) * wb.x +
        fmaxf(d1y * rs * ga1.y + gb1.y, 0.f) * wb.y +
        fmaxf(d1z * rs * ga1.z + gb1.z, 0.f) * wb.z +
        fmaxf(d1w * rs * ga1.w + gb1.w, 0.f) * wb.w;
#pragma unroll
    for (int o = 16; o; o >>= 1) dot += __shfl_xor_sync(0xffffffffu, dot, o);
    if (lane == 0) g_gate[row] = dot + b2[0];
}

// ---------------- segment softmax + weighted pool (block per graph) --------
__global__ __launch_bounds__(128) void k_pool() {
    __shared__ float w[64];
    int b = blockIdx.x;
    int tid = threadIdx.x;
    if (tid < 32) {
        float g0 = g_gate[b * 64 + tid];
        float g1 = g_gate[b * 64 + 32 + tid];
        float m = fmaxf(g0, g1);
#pragma unroll
        for (int o = 16; o; o >>= 1) m = fmaxf(m, __shfl_xor_sync(0xffffffffu, m, o));
        float e0 = expf(g0 - m), e1 = expf(g1 - m);
        float s = e0 + e1;
#pragma unroll
        for (int o = 16; o; o >>= 1) s += __shfl_xor_sync(0xffffffffu, s, o);
        w[tid] = e0 / s;
        w[tid + 32] = e1 / s;
    }
    __syncthreads();
    float acc = 0.f;
#pragma unroll 8
    for (int i = 0; i < 64; i++) acc += w[i] * g_x[(b * 64 + i) * DD + tid];
    g_pool[b * DD + tid] = acc;
}

// ---------------- tail: 2 residual blocks + head (block per graph) ---------
__device__ __forceinline__ float block_ln(float v, float g, float bt, float* red) {
    int lane = threadIdx.x & 31, wid = threadIdx.x >> 5;
    float s = v;
#pragma unroll
    for (int o = 16; o; o >>= 1) s += __shfl_xor_sync(0xffffffffu, s, o);
    if (lane == 0) red[wid] = s;
    __syncthreads();
    float mu = (red[0] + red[1] + red[2] + red[3]) * (1.f / 128.f);
    float d = v - mu;
    float q = d * d;
#pragma unroll
    for (int o = 16; o; o >>= 1) q += __shfl_xor_sync(0xffffffffu, q, o);
    if (lane == 0) red[4 + wid] = q;
    __syncthreads();
    float var = (red[4] + red[5] + red[6] + red[7]) * (1.f / 128.f);
    float out = d * rsqrtf(var + 1e-5f) * g + bt;
    __syncthreads();
    return out;
}

__global__ __launch_bounds__(128) void k_tail(
    const float* __restrict__ fc1W, const float* __restrict__ fc1b,
    const float* __restrict__ ln1g, const float* __restrict__ ln1b,
    const float* __restrict__ fc2W, const float* __restrict__ fc2b,
    const float* __restrict__ ln2g, const float* __restrict__ ln2b,
    const float* __restrict__ pW1, const float* __restrict__ pb1,
    const float* __restrict__ pW2, const float* __restrict__ pb2,
    float* __restrict__ out) {
    __shared__ float sg[128], sh[128], red[8];
    int b = blockIdx.x, n = threadIdx.x;
    sg[n] = g_pool[b * DD + n];
    __syncthreads();
#pragma unroll
    for (int r = 0; r < 2; r++) {
        const float* W1 = fc1W + r * DD * DD;
        const float* W2 = fc2W + r * DD * DD;
        float u = fc1b[r * DD + n];
#pragma unroll 16
        for (int k = 0; k < 128; k++) u += sg[k] * W1[k * DD + n];
        float hn = gelu_erf(block_ln(u, ln1g[r * DD + n], ln1b[r * DD + n], red));
        sh[n] = hn;
        __syncthreads();
        float v2 = fc2b[r * DD + n];
#pragma unroll 16
        for (int k = 0; k < 128; k++) v2 += sh[k] * W2[k * DD + n];
        float h2 = block_ln(v2, ln2g[r * DD + n], ln2b[r * DD + n], red);
        sg[n] += h2;
        __syncthreads();
    }
    float u = pb1[n];
#pragma unroll 16
    for (int k = 0; k < 128; k++) u += sg[k] * pW1[k * DD + n];
    sh[n] = gelu_erf(u);
    __syncthreads();
    if (n < 12) {
        float o = pb2[n];
#pragma unroll 16
        for (int k = 0; k < 128; k++) o += sh[k] * pW2[k * 12 + n];
        out[b * 12 + n] = o;
    }
}

// ---------------- launch ----------------
extern "C" void kernel_launch(void* const* d_in, const int* in_sizes, int n_in,
                              void* d_out, int out_size) {
    const float* logits   = (const float*)d_in[0];
    // d_in[1] atom_mask: statically known, unused
    const int*   atom_feature = (const int*)d_in[2];
    const int*   edge_index   = (const int*)d_in[3];
    const int*   edge_attr    = (const int*)d_in[4];
    // d_in[5] batch_idx: statically known, unused
    const float* atom_emb = (const float*)d_in[6];
    const float* edge_emb = (const float*)d_in[7];
    const float* gnn_W1 = (const float*)d_in[8];
    const float* gnn_b1 = (const float*)d_in[9];
    const float* gnn_W2 = (const float*)d_in[10];
    const float* gnn_b2 = (const float*)d_in[11];
    const float* gnn_ln_g = (const float*)d_in[12];
    const float* gnn_ln_b = (const float*)d_in[13];
    const float* gate_W1 = (const float*)d_in[14];
    const float* gate_b1 = (const float*)d_in[15];
    const float* gate_ln_g = (const float*)d_in[16];
    const float* gate_ln_b = (const float*)d_in[17];
    const float* gate_W2 = (const float*)d_in[18];
    const float* gate_b2 = (const float*)d_in[19];
    const float* res_fc1_W = (const float*)d_in[20];
    const float* res_fc1_b = (const float*)d_in[21];
    const float* res_ln1_g = (const float*)d_in[22];
    const float* res_ln1_b = (const float*)d_in[23];
    const float* res_fc2_W = (const float*)d_in[24];
    const float* res_fc2_b = (const float*)d_in[25];
    const float* res_ln2_g = (const float*)d_in[26];
    const float* res_ln2_b = (const float*)d_in[27];
    const float* pred_W1 = (const float*)d_in[28];
    const float* pred_b1 = (const float*)d_in[29];
    const float* pred_W2 = (const float*)d_in[30];
    const float* pred_b2 = (const float*)d_in[31];
    float* out = (float*)d_out;

    const int* e_src = edge_index;
    const int* e_dst = edge_index + NE;

    float *xp, *aggp, *tp, *hp;
    cudaGetSymbolAddress((void**)&xp, g_x);
    cudaGetSymbolAddress((void**)&aggp, g_agg);
    cudaGetSymbolAddress((void**)&tp, g_t);
    cudaGetSymbolAddress((void**)&hp, g_h);

    k_build_x<<<NN, 128>>>(logits, atom_feature, atom_emb);
    k_zero_counts<<<NN / 256, 256>>>();
    k_hist<<<NE / 512, 256>>>(e_dst);
    k_scan1<<<32, 1024>>>();
    k_scan2<<<1, 32>>>();
    k_scan3<<<32, 1024>>>();
    k_scatter<<<NE / 512, 256>>>(e_src, e_dst, edge_attr);

    for (int l = 0; l < 3; l++) {
        k_aggregate<<<NN / 8, 256>>>(edge_emb);
        k_mma_gemm<<<dim3(NN / 128, HID / 64), 256>>>(aggp, gnn_W1 + l * DD * HID,
                                                      gnn_b1 + l * HID, tp, DD, HID, 1);
        k_mma_gemm<<<dim3(NN / 128, DD / 64), 256>>>(tp, gnn_W2 + l * HID * DD,
                                                     gnn_b2 + l * DD, hp, HID, DD, 0);
        k_ln_residual<<<NN / 8, 256>>>(hp, gnn_ln_g + l * DD, gnn_ln_b + l * DD);
    }

    k_mma_gemm<<<dim3(NN / 128, HID / 64), 256>>>(xp, gate_W1, gate_b1, tp, DD, HID, 0);
    k_gate_finish<<<NN / 8, 256>>>(gate_ln_g, gate_ln_b, gate_W2, gate_b2);
    k_pool<<<NB, 128>>>();
    k_tail<<<NB, 128>>>(res_fc1_W, res_fc1_b, res_ln1_g, res_ln1_b,
                        res_fc2_W, res_fc2_b, res_ln2_g, res_ln2_b,
                        pred_W1, pred_b1, pred_W2, pred_b2, out);
}

// round 7
// speedup vs baseline: 1.2572x; 1.0872x over previous
#include <cuda_runtime.h>
#include <cuda_fp16.h>
#include <math.h>
#include <stdint.h>

#define NN 32768          // nodes
#define NE 524288         // edges
#define DD 128
#define NB 512            // graphs
#define HID 256

// ---------------- scratch (device globals; no allocation allowed) ----------
__device__ __align__(16) float g_x[NN * DD];
__device__ __align__(16) __half g_xh[NN * DD];    // fp16 mirror of x
__device__ __align__(16) __half g_aggh[NN * DD];  // fp16 aggregate
__device__ __align__(16) __half g_th[NN * HID];   // fp16 hidden
__device__ __align__(16) float g_t[NN * HID];     // fp32 hidden (gate path)
__device__ __align__(16) float g_h[NN * DD];
__device__ float g_gate[NN];
__device__ __align__(16) float g_pool[NB * DD];
__device__ int g_counts[NN];
__device__ int g_off[NN + 1];
__device__ int g_cursor[NN];
__device__ int g_bsum[32];
__device__ int g_boff[32];
__device__ int g_pe[NE];        // packed (src<<3)|attr

// ---------------- helpers ----------------
__device__ __forceinline__ float gelu_erf(float x) {
    return 0.5f * x * (1.0f + erff(x * 0.70710678118654752f));
}

// ---------------- build x = logits[masked] + atom_emb[feat] ----------------
__global__ void k_build_x(const float* __restrict__ logits,
                          const int* __restrict__ af,
                          const float* __restrict__ aemb) {
    int node = blockIdx.x;
    int d = threadIdx.x;
    int b = node >> 6, a = node & 63;
    float v = logits[b * (128 * DD) + a * DD + d] + aemb[af[node] * DD + d];
    g_x[node * DD + d] = v;
    g_xh[node * DD + d] = __float2half(v);
}

// ---------------- CSR build ----------------
__global__ void k_zero_counts() {
    int i = blockIdx.x * blockDim.x + threadIdx.x;
    if (i < NN) g_counts[i] = 0;
}
__global__ void k_hist(const int* __restrict__ dst) {
    int e = blockIdx.x * blockDim.x + threadIdx.x;
    atomicAdd(&g_counts[dst[e]], 1);
    atomicAdd(&g_counts[dst[e + NE / 2]], 1);
}
__global__ __launch_bounds__(1024) void k_scan1() {
    __shared__ int sh[1024];
    int b = blockIdx.x, t = threadIdx.x, i = b * 1024 + t;
    int v = g_counts[i];
    sh[t] = v;
    __syncthreads();
    for (int o = 1; o < 1024; o <<= 1) {
        int u = 0;
        if (t >= o) u = sh[t - o];
        __syncthreads();
        sh[t] += u;
        __syncthreads();
    }
    g_off[i] = sh[t] - v;     // exclusive
    if (t == 1023) g_bsum[b] = sh[1023];
}
__global__ void k_scan2() {
    int t = threadIdx.x;
    int v = g_bsum[t];
    int s = v;
#pragma unroll
    for (int o = 1; o < 32; o <<= 1) {
        int u = __shfl_up_sync(0xffffffffu, s, o);
        if (t >= o) s += u;
    }
    g_boff[t] = s - v;
}
__global__ __launch_bounds__(1024) void k_scan3() {
    int b = blockIdx.x, t = threadIdx.x, i = b * 1024 + t;
    int o = g_off[i] + g_boff[b];
    g_off[i] = o;
    g_cursor[i] = o;
    if (i == 0) g_off[NN] = NE;
}
__global__ void k_scatter(const int* __restrict__ src,
                          const int* __restrict__ dst,
                          const int* __restrict__ attr) {
    int e = blockIdx.x * blockDim.x + threadIdx.x;
#pragma unroll
    for (int h = 0; h < 2; h++) {
        int ee = e + h * (NE / 2);
        int p = atomicAdd(&g_cursor[dst[ee]], 1);
        g_pe[p] = (src[ee] << 3) | attr[ee];
    }
}

// ---------------- edge aggregation: aggh[i] = sum relu(x[src]+eemb[attr]) --
__global__ __launch_bounds__(256) void k_aggregate(const float* __restrict__ eemb_g) {
    __shared__ float eemb[8 * DD];
    for (int i = threadIdx.x; i < 8 * DD; i += 256) eemb[i] = eemb_g[i];
    __syncthreads();
    int warp = (blockIdx.x * 256 + threadIdx.x) >> 5;
    int lane = threadIdx.x & 31;
    int s = g_off[warp], e = g_off[warp + 1];
    float4 acc = make_float4(0.f, 0.f, 0.f, 0.f);
    const float* emb = &eemb[(lane * 4)];
    for (int j = s; j < e; j++) {
        int p = g_pe[j];
        int sn = p >> 3;
        const float* em = emb + (p & 7) * DD;
        uint2 hv = *(const uint2*)&g_xh[sn * DD + lane * 4];
        float2 f0 = __half22float2(*(const __half2*)&hv.x);
        float2 f1 = __half22float2(*(const __half2*)&hv.y);
        acc.x += fmaxf(f0.x + em[0], 0.f);
        acc.y += fmaxf(f0.y + em[1], 0.f);
        acc.z += fmaxf(f1.x + em[2], 0.f);
        acc.w += fmaxf(f1.y + em[3], 0.f);
    }
    __half2 h0 = __floats2half2_rn(acc.x, acc.y);
    __half2 h1 = __floats2half2_rn(acc.z, acc.w);
    uint2 ov;
    ov.x = *(uint32_t*)&h0;
    ov.y = *(uint32_t*)&h1;
    *(uint2*)&g_aggh[warp * DD + lane * 4] = ov;
}

// ---------------- FP16 tensor-core GEMM ------------------------------------
// C[M,N] = act(A[M,K] @ W[K,N] + bias); A fp16 row-major, W fp32 (converted).
// CTA tile 128x64, BK=32, 8 warps (4M x 2N), warp tile 32x32, mma.m16n8k16.
#define AS_STRIDE 40   // halves (80B) — conflict-free frag loads
#define WS_STRIDE 42   // halves (84B) — transposed W tile [n][k]
template <int RELU, int OUTHALF>
__global__ __launch_bounds__(256) void k_hgemm(const __half* __restrict__ A,
                                               const float* __restrict__ W,
                                               const float* __restrict__ bias,
                                               void* __restrict__ Cout,
                                               int K, int N) {
    __shared__ __align__(16) __half As[128 * AS_STRIDE];
    __shared__ __align__(16) __half Ws[64 * WS_STRIDE];
    int tid = threadIdx.x;
    int lane = tid & 31;
    int wid = tid >> 5;
    int warp_m = (wid >> 1) * 32;
    int warp_n = (wid & 1) * 32;
    int m0 = blockIdx.x * 128;
    int n0 = blockIdx.y * 64;
    int gid = lane >> 2;
    int tig = lane & 3;

    float acc[2][4][4];
#pragma unroll
    for (int i = 0; i < 2; i++)
#pragma unroll
        for (int j = 0; j < 4; j++)
#pragma unroll
            for (int c = 0; c < 4; c++) acc[i][j][c] = 0.f;

    for (int k0 = 0; k0 < K; k0 += 32) {
        // A tile: 128 x 32 halves, direct copy
        {
            int r = tid >> 2;            // 0..63
            int c8 = (tid & 3) * 8;      // half offset
#pragma unroll
            for (int p = 0; p < 2; p++) {
                int row = r + p * 64;
                uint4 v = *(const uint4*)&A[(size_t)(m0 + row) * K + k0 + c8];
                *(uint4*)&As[row * AS_STRIDE + c8] = v;
            }
        }
        // W tile: 32 x 64 fp32 -> transposed Ws[n][k] fp16
        {
            int wr = tid >> 4;           // 0..15
            int c4 = (tid & 15) * 4;
#pragma unroll
            for (int p = 0; p < 2; p++) {
                int k = wr + p * 16;
                float4 v = *(const float4*)&W[(size_t)(k0 + k) * N + n0 + c4];
                Ws[(c4 + 0) * WS_STRIDE + k] = __float2half(v.x);
                Ws[(c4 + 1) * WS_STRIDE + k] = __float2half(v.y);
                Ws[(c4 + 2) * WS_STRIDE + k] = __float2half(v.z);
                Ws[(c4 + 3) * WS_STRIDE + k] = __float2half(v.w);
            }
        }
        __syncthreads();
#pragma unroll
        for (int kk = 0; kk < 32; kk += 16) {
            uint32_t af[2][4];
#pragma unroll
            for (int mi = 0; mi < 2; mi++) {
                int mb = warp_m + mi * 16;
                const __half* a0 = &As[(mb + gid) * AS_STRIDE + kk + tig * 2];
                const __half* a1 = &As[(mb + gid + 8) * AS_STRIDE + kk + tig * 2];
                af[mi][0] = *(const uint32_t*)a0;
                af[mi][1] = *(const uint32_t*)a1;
                af[mi][2] = *(const uint32_t*)(a0 + 8);
                af[mi][3] = *(const uint32_t*)(a1 + 8);
            }
            uint32_t bf[4][2];
#pragma unroll
            for (int ni = 0; ni < 4; ni++) {
                int nb = warp_n + ni * 8;
                const __half* b0 = &Ws[(nb + gid) * WS_STRIDE + kk + tig * 2];
                bf[ni][0] = *(const uint32_t*)b0;
                bf[ni][1] = *(const uint32_t*)(b0 + 8);
            }
#pragma unroll
            for (int mi = 0; mi < 2; mi++)
#pragma unroll
                for (int ni = 0; ni < 4; ni++) {
                    asm volatile(
                        "mma.sync.aligned.m16n8k16.row.col.f32.f16.f16.f32 "
                        "{%0,%1,%2,%3}, {%4,%5,%6,%7}, {%8,%9}, {%0,%1,%2,%3};"
                        : "+f"(acc[mi][ni][0]), "+f"(acc[mi][ni][1]),
                          "+f"(acc[mi][ni][2]), "+f"(acc[mi][ni][3])
                        : "r"(af[mi][0]), "r"(af[mi][1]),
                          "r"(af[mi][2]), "r"(af[mi][3]),
                          "r"(bf[ni][0]), "r"(bf[ni][1]));
                }
        }
        __syncthreads();
    }
#pragma unroll
    for (int mi = 0; mi < 2; mi++) {
        int row0 = m0 + warp_m + mi * 16 + gid;
#pragma unroll
        for (int ni = 0; ni < 4; ni++) {
            int col = n0 + warp_n + ni * 8 + tig * 2;
            float b0 = bias[col], b1 = bias[col + 1];
            float2 o0 = make_float2(acc[mi][ni][0] + b0, acc[mi][ni][1] + b1);
            float2 o1 = make_float2(acc[mi][ni][2] + b0, acc[mi][ni][3] + b1);
            if (RELU) {
                o0.x = fmaxf(o0.x, 0.f); o0.y = fmaxf(o0.y, 0.f);
                o1.x = fmaxf(o1.x, 0.f); o1.y = fmaxf(o1.y, 0.f);
            }
            if (OUTHALF) {
                __half* C = (__half*)Cout;
                *(__half2*)&C[(size_t)row0 * N + col] = __floats2half2_rn(o0.x, o0.y);
                *(__half2*)&C[(size_t)(row0 + 8) * N + col] = __floats2half2_rn(o1.x, o1.y);
            } else {
                float* C = (float*)Cout;
                *(float2*)&C[(size_t)row0 * N + col] = o0;
                *(float2*)&C[(size_t)(row0 + 8) * N + col] = o1;
            }
        }
    }
}

// ---------------- x += LN(h); refresh fp16 mirror (per row, warp) ----------
__global__ __launch_bounds__(256) void k_ln_residual(const float* __restrict__ h,
                                                     const float* __restrict__ gam,
                                                     const float* __restrict__ bet) {
    int row = (blockIdx.x * 256 + threadIdx.x) >> 5;
    int lane = threadIdx.x & 31;
    float4 v = *(const float4*)&h[row * DD + lane * 4];
    float s = v.x + v.y + v.z + v.w;
#pragma unroll
    for (int o = 16; o; o >>= 1) s += __shfl_xor_sync(0xffffffffu, s, o);
    float mu = s * (1.f / 128.f);
    float dx = v.x - mu, dy = v.y - mu, dz = v.z - mu, dw = v.w - mu;
    float q = dx * dx + dy * dy + dz * dz + dw * dw;
#pragma unroll
    for (int o = 16; o; o >>= 1) q += __shfl_xor_sync(0xffffffffu, q, o);
    float rs = rsqrtf(q * (1.f / 128.f) + 1e-5f);
    float4 g4 = *(const float4*)&gam[lane * 4];
    float4 b4 = *(const float4*)&bet[lane * 4];
    float4 xo = *(const float4*)&g_x[row * DD + lane * 4];
    xo.x += dx * rs * g4.x + b4.x;
    xo.y += dy * rs * g4.y + b4.y;
    xo.z += dz * rs * g4.z + b4.z;
    xo.w += dw * rs * g4.w + b4.w;
    *(float4*)&g_x[row * DD + lane * 4] = xo;
    __half2 h0 = __floats2half2_rn(xo.x, xo.y);
    __half2 h1 = __floats2half2_rn(xo.z, xo.w);
    uint2 hv;
    hv.x = *(uint32_t*)&h0;
    hv.y = *(uint32_t*)&h1;
    *(uint2*)&g_xh[row * DD + lane * 4] = hv;
}

// ---------------- gate = relu(LN256(t)) . W2 + b2 (per row, warp) ----------
__global__ __launch_bounds__(256) void k_gate_finish(const float* __restrict__ gam,
                                                     const float* __restrict__ bet,
                                                     const float* __restrict__ w2,
                                                     const float* __restrict__ b2) {
    int row = (blockIdx.x * 256 + threadIdx.x) >> 5;
    int lane = threadIdx.x & 31;
    float4 v0 = *(const float4*)&g_t[row * HID + lane * 4];
    float4 v1 = *(const float4*)&g_t[row * HID + 128 + lane * 4];
    float s = v0.x + v0.y + v0.z + v0.w + v1.x + v1.y + v1.z + v1.w;
#pragma unroll
    for (int o = 16; o; o >>= 1) s += __shfl_xor_sync(0xffffffffu, s, o);
    float mu = s * (1.f / 256.f);
    float d0x = v0.x - mu, d0y = v0.y - mu, d0z = v0.z - mu, d0w = v0.w - mu;
    float d1x = v1.x - mu, d1y = v1.y - mu, d1z = v1.z - mu, d1w = v1.w - mu;
    float q = d0x * d0x + d0y * d0y + d0z * d0z + d0w * d0w +
              d1x * d1x + d1y * d1y + d1z * d1z + d1w * d1w;
#pragma unroll
    for (int o = 16; o; o >>= 1) q += __shfl_xor_sync(0xffffffffu, q, o);
    float rs = rsqrtf(q * (1.f / 256.f) + 1e-5f);
    float4 ga = *(const float4*)&gam[lane * 4];
    float4 gb = *(const float4*)&bet[lane * 4];
    float4 ga1 = *(const float4*)&gam[128 + lane * 4];
    float4 gb1 = *(const float4*)&bet[128 + lane * 4];
    float4 wa = *(const float4*)&w2[lane * 4];
    float4 wb = *(const float4*)&w2[128 + lane * 4];
    float dot =
        fmaxf(d0x * rs * ga.x + gb.x, 0.f) * wa.x +
        fmaxf(d0y * rs * ga.y + gb.y, 0.f) * wa.y +
        fmaxf(d0z * rs * ga.z + gb.z, 0.f) * wa.z +
        fmaxf(d0w * rs * ga.w + gb.w, 0.f) * wa.w +
        fmaxf(d1x * rs * ga1.x + gb1.x, 0.f) * wb.x +
        fmaxf(d1y * rs * ga1.y + gb1.y, 0.f) * wb.y +
        fmaxf(d1z * rs * ga1.z + gb1.z, 0.f) * wb.z +
        fmaxf(d1w * rs * ga1.w + gb1.w, 0.f) * wb.w;
#pragma unroll
    for (int o = 16; o; o >>= 1) dot += __shfl_xor_sync(0xffffffffu, dot, o);
    if (lane == 0) g_gate[row] = dot + b2[0];
}

// ---------------- segment softmax + weighted pool (block per graph) --------
__global__ __launch_bounds__(128) void k_pool() {
    __shared__ float w[64];
    int b = blockIdx.x;
    int tid = threadIdx.x;
    if (tid < 32) {
        float g0 = g_gate[b * 64 + tid];
        float g1 = g_gate[b * 64 + 32 + tid];
        float m = fmaxf(g0, g1);
#pragma unroll
        for (int o = 16; o; o >>= 1) m = fmaxf(m, __shfl_xor_sync(0xffffffffu, m, o));
        float e0 = expf(g0 - m), e1 = expf(g1 - m);
        float s = e0 + e1;
#pragma unroll
        for (int o = 16; o; o >>= 1) s += __shfl_xor_sync(0xffffffffu, s, o);
        w[tid] = e0 / s;
        w[tid + 32] = e1 / s;
    }
    __syncthreads();
    float acc = 0.f;
#pragma unroll 8
    for (int i = 0; i < 64; i++) acc += w[i] * g_x[(b * 64 + i) * DD + tid];
    g_pool[b * DD + tid] = acc;
}

// ---------------- tail: 2 residual blocks + head (block per graph) ---------
__device__ __forceinline__ float block_ln(float v, float g, float bt, float* red) {
    int lane = threadIdx.x & 31, wid = threadIdx.x >> 5;
    float s = v;
#pragma unroll
    for (int o = 16; o; o >>= 1) s += __shfl_xor_sync(0xffffffffu, s, o);
    if (lane == 0) red[wid] = s;
    __syncthreads();
    float mu = (red[0] + red[1] + red[2] + red[3]) * (1.f / 128.f);
    float d = v - mu;
    float q = d * d;
#pragma unroll
    for (int o = 16; o; o >>= 1) q += __shfl_xor_sync(0xffffffffu, q, o);
    if (lane == 0) red[4 + wid] = q;
    __syncthreads();
    float var = (red[4] + red[5] + red[6] + red[7]) * (1.f / 128.f);
    float out = d * rsqrtf(var + 1e-5f) * g + bt;
    __syncthreads();
    return out;
}

__global__ __launch_bounds__(128) void k_tail(
    const float* __restrict__ fc1W, const float* __restrict__ fc1b,
    const float* __restrict__ ln1g, const float* __restrict__ ln1b,
    const float* __restrict__ fc2W, const float* __restrict__ fc2b,
    const float* __restrict__ ln2g, const float* __restrict__ ln2b,
    const float* __restrict__ pW1, const float* __restrict__ pb1,
    const float* __restrict__ pW2, const float* __restrict__ pb2,
    float* __restrict__ out) {
    __shared__ float sg[128], sh[128], red[8];
    int b = blockIdx.x, n = threadIdx.x;
    sg[n] = g_pool[b * DD + n];
    __syncthreads();
#pragma unroll
    for (int r = 0; r < 2; r++) {
        const float* W1 = fc1W + r * DD * DD;
        const float* W2 = fc2W + r * DD * DD;
        float u = fc1b[r * DD + n];
#pragma unroll 16
        for (int k = 0; k < 128; k++) u += sg[k] * W1[k * DD + n];
        float hn = gelu_erf(block_ln(u, ln1g[r * DD + n], ln1b[r * DD + n], red));
        sh[n] = hn;
        __syncthreads();
        float v2 = fc2b[r * DD + n];
#pragma unroll 16
        for (int k = 0; k < 128; k++) v2 += sh[k] * W2[k * DD + n];
        float h2 = block_ln(v2, ln2g[r * DD + n], ln2b[r * DD + n], red);
        sg[n] += h2;
        __syncthreads();
    }
    float u = pb1[n];
#pragma unroll 16
    for (int k = 0; k < 128; k++) u += sg[k] * pW1[k * DD + n];
    sh[n] = gelu_erf(u);
    __syncthreads();
    if (n < 12) {
        float o = pb2[n];
#pragma unroll 16
        for (int k = 0; k < 128; k++) o += sh[k] * pW2[k * 12 + n];
        out[b * 12 + n] = o;
    }
}

// ---------------- launch ----------------
extern "C" void kernel_launch(void* const* d_in, const int* in_sizes, int n_in,
                              void* d_out, int out_size) {
    const float* logits   = (const float*)d_in[0];
    const int*   atom_feature = (const int*)d_in[2];
    const int*   edge_index   = (const int*)d_in[3];
    const int*   edge_attr    = (const int*)d_in[4];
    const float* atom_emb = (const float*)d_in[6];
    const float* edge_emb = (const float*)d_in[7];
    const float* gnn_W1 = (const float*)d_in[8];
    const float* gnn_b1 = (const float*)d_in[9];
    const float* gnn_W2 = (const float*)d_in[10];
    const float* gnn_b2 = (const float*)d_in[11];
    const float* gnn_ln_g = (const float*)d_in[12];
    const float* gnn_ln_b = (const float*)d_in[13];
    const float* gate_W1 = (const float*)d_in[14];
    const float* gate_b1 = (const float*)d_in[15];
    const float* gate_ln_g = (const float*)d_in[16];
    const float* gate_ln_b = (const float*)d_in[17];
    const float* gate_W2 = (const float*)d_in[18];
    const float* gate_b2 = (const float*)d_in[19];
    const float* res_fc1_W = (const float*)d_in[20];
    const float* res_fc1_b = (const float*)d_in[21];
    const float* res_ln1_g = (const float*)d_in[22];
    const float* res_ln1_b = (const float*)d_in[23];
    const float* res_fc2_W = (const float*)d_in[24];
    const float* res_fc2_b = (const float*)d_in[25];
    const float* res_ln2_g = (const float*)d_in[26];
    const float* res_ln2_b = (const float*)d_in[27];
    const float* pred_W1 = (const float*)d_in[28];
    const float* pred_b1 = (const float*)d_in[29];
    const float* pred_W2 = (const float*)d_in[30];
    const float* pred_b2 = (const float*)d_in[31];
    float* out = (float*)d_out;

    const int* e_src = edge_index;
    const int* e_dst = edge_index + NE;

    __half *agghp, *thp, *xhp;
    float *tp, *hp;
    cudaGetSymbolAddress((void**)&agghp, g_aggh);
    cudaGetSymbolAddress((void**)&thp, g_th);
    cudaGetSymbolAddress((void**)&xhp, g_xh);
    cudaGetSymbolAddress((void**)&tp, g_t);
    cudaGetSymbolAddress((void**)&hp, g_h);

    k_build_x<<<NN, 128>>>(logits, atom_feature, atom_emb);
    k_zero_counts<<<NN / 256, 256>>>();
    k_hist<<<NE / 512, 256>>>(e_dst);
    k_scan1<<<32, 1024>>>();
    k_scan2<<<1, 32>>>();
    k_scan3<<<32, 1024>>>();
    k_scatter<<<NE / 512, 256>>>(e_src, e_dst, edge_attr);

    for (int l = 0; l < 3; l++) {
        k_aggregate<<<NN / 8, 256>>>(edge_emb);
        k_hgemm<1, 1><<<dim3(NN / 128, HID / 64), 256>>>(
            agghp, gnn_W1 + l * DD * HID, gnn_b1 + l * HID, thp, DD, HID);
        k_hgemm<0, 0><<<dim3(NN / 128, DD / 64), 256>>>(
            thp, gnn_W2 + l * HID * DD, gnn_b2 + l * DD, hp, HID, DD);
        k_ln_residual<<<NN / 8, 256>>>(hp, gnn_ln_g + l * DD, gnn_ln_b + l * DD);
    }

    k_hgemm<0, 0><<<dim3(NN / 128, HID / 64), 256>>>(
        xhp, gate_W1, gate_b1, tp, DD, HID);
    k_gate_finish<<<NN / 8, 256>>>(gate_ln_g, gate_ln_b, gate_W2, gate_b2);
    k_pool<<<NB, 128>>>();
    k_tail<<<NB, 128>>>(res_fc1_W, res_fc1_b, res_ln1_g, res_ln1_b,
                        res_fc2_W, res_fc2_b, res_ln2_g, res_ln2_b,
                        pred_W1, pred_b1, pred_W2, pred_b2, out);
}

// round 10
// speedup vs baseline: 1.2645x; 1.0058x over previous
#include <cuda_runtime.h>
#include <cuda_fp16.h>
#include <math.h>
#include <stdint.h>

#define NN 32768          // nodes
#define NE 524288         // edges
#define DD 128
#define NB 512            // graphs
#define HID 256

// ---------------- scratch (device globals; no allocation allowed) ----------
__device__ __align__(16) float g_x[NN * DD];
__device__ __align__(16) __half g_xh[NN * DD];    // fp16 mirror of x
__device__ __align__(16) __half g_aggh[NN * DD];  // fp16 aggregate
__device__ __align__(16) __half g_th[NN * HID];   // fp16 hidden
__device__ __align__(16) float g_t[NN * HID];     // fp32 hidden (gate path)
__device__ __align__(16) float g_h[NN * DD];
__device__ float g_gate[NN];
__device__ int g_counts[NN];
__device__ int g_off[NN + 1];
__device__ int g_cursor[NN];
__device__ int g_bsum[32];
__device__ int g_boff[32];
__device__ int g_pe[NE];        // packed (src<<3)|attr

// ---------------- helpers ----------------
__device__ __forceinline__ float gelu_erf(float x) {
    return 0.5f * x * (1.0f + erff(x * 0.70710678118654752f));
}

// ---------------- build x = logits[masked] + atom_emb[feat] ----------------
__global__ void k_build_x(const float* __restrict__ logits,
                          const int* __restrict__ af,
                          const float* __restrict__ aemb) {
    int node = blockIdx.x;
    int d = threadIdx.x;
    int b = node >> 6, a = node & 63;
    float v = logits[b * (128 * DD) + a * DD + d] + aemb[af[node] * DD + d];
    g_x[node * DD + d] = v;
    g_xh[node * DD + d] = __float2half(v);
}

// ---------------- CSR build ----------------
__global__ void k_zero_counts() {
    int i = blockIdx.x * blockDim.x + threadIdx.x;
    if (i < NN) g_counts[i] = 0;
}
__global__ void k_hist(const int* __restrict__ dst) {
    int e = blockIdx.x * blockDim.x + threadIdx.x;
    atomicAdd(&g_counts[dst[e]], 1);
    atomicAdd(&g_counts[dst[e + NE / 2]], 1);
}
__global__ __launch_bounds__(1024) void k_scan1() {
    __shared__ int sh[1024];
    int b = blockIdx.x, t = threadIdx.x, i = b * 1024 + t;
    int v = g_counts[i];
    sh[t] = v;
    __syncthreads();
    for (int o = 1; o < 1024; o <<= 1) {
        int u = 0;
        if (t >= o) u = sh[t - o];
        __syncthreads();
        sh[t] += u;
        __syncthreads();
    }
    g_off[i] = sh[t] - v;     // exclusive
    if (t == 1023) g_bsum[b] = sh[1023];
}
__global__ void k_scan2() {
    int t = threadIdx.x;
    int v = g_bsum[t];
    int s = v;
#pragma unroll
    for (int o = 1; o < 32; o <<= 1) {
        int u = __shfl_up_sync(0xffffffffu, s, o);
        if (t >= o) s += u;
    }
    g_boff[t] = s - v;
}
__global__ __launch_bounds__(1024) void k_scan3() {
    int b = blockIdx.x, t = threadIdx.x, i = b * 1024 + t;
    int o = g_off[i] + g_boff[b];
    g_off[i] = o;
    g_cursor[i] = o;
    if (i == 0) g_off[NN] = NE;
}
__global__ void k_scatter(const int* __restrict__ src,
                          const int* __restrict__ dst,
                          const int* __restrict__ attr) {
    int e = blockIdx.x * blockDim.x + threadIdx.x;
#pragma unroll
    for (int h = 0; h < 2; h++) {
        int ee = e + h * (NE / 2);
        int p = atomicAdd(&g_cursor[dst[ee]], 1);
        g_pe[p] = (src[ee] << 3) | attr[ee];
    }
}

// ---------------- edge aggregation: aggh[i] = sum relu(x[src]+eemb[attr]) --
// warp per node; 8-deep software pipeline on the gathers (MLP ~8)
__global__ __launch_bounds__(256) void k_aggregate(const float* __restrict__ eemb_g) {
    __shared__ float eemb[8 * DD];
    for (int i = threadIdx.x; i < 8 * DD; i += 256) eemb[i] = eemb_g[i];
    __syncthreads();
    int warp = (blockIdx.x * 256 + threadIdx.x) >> 5;
    int lane = threadIdx.x & 31;
    int s = g_off[warp], e = g_off[warp + 1];
    float4 acc = make_float4(0.f, 0.f, 0.f, 0.f);
    const float* emb = &eemb[lane * 4];
    int j = s;
    for (; j + 8 <= e; j += 8) {
        int p[8];
        uint2 v[8];
#pragma unroll
        for (int u = 0; u < 8; u++) p[u] = g_pe[j + u];
#pragma unroll
        for (int u = 0; u < 8; u++)
            v[u] = *(const uint2*)&g_xh[(size_t)(p[u] >> 3) * DD + lane * 4];
#pragma unroll
        for (int u = 0; u < 8; u++) {
            const float* em = emb + (p[u] & 7) * DD;
            float2 f0 = __half22float2(*(const __half2*)&v[u].x);
            float2 f1 = __half22float2(*(const __half2*)&v[u].y);
            acc.x += fmaxf(f0.x + em[0], 0.f);
            acc.y += fmaxf(f0.y + em[1], 0.f);
            acc.z += fmaxf(f1.x + em[2], 0.f);
            acc.w += fmaxf(f1.y + em[3], 0.f);
        }
    }
    for (; j < e; j++) {
        int p = g_pe[j];
        const float* em = emb + (p & 7) * DD;
        uint2 hv = *(const uint2*)&g_xh[(size_t)(p >> 3) * DD + lane * 4];
        float2 f0 = __half22float2(*(const __half2*)&hv.x);
        float2 f1 = __half22float2(*(const __half2*)&hv.y);
        acc.x += fmaxf(f0.x + em[0], 0.f);
        acc.y += fmaxf(f0.y + em[1], 0.f);
        acc.z += fmaxf(f1.x + em[2], 0.f);
        acc.w += fmaxf(f1.y + em[3], 0.f);
    }
    __half2 h0 = __floats2half2_rn(acc.x, acc.y);
    __half2 h1 = __floats2half2_rn(acc.z, acc.w);
    uint2 ov;
    ov.x = *(uint32_t*)&h0;
    ov.y = *(uint32_t*)&h1;
    *(uint2*)&g_aggh[warp * DD + lane * 4] = ov;
}

// ---------------- FP16 tensor-core GEMM ------------------------------------
#define AS_STRIDE 40
#define WS_STRIDE 42
template <int RELU, int OUTHALF>
__global__ __launch_bounds__(256) void k_hgemm(const __half* __restrict__ A,
                                               const float* __restrict__ W,
                                               const float* __restrict__ bias,
                                               void* __restrict__ Cout,
                                               int K, int N) {
    __shared__ __align__(16) __half As[128 * AS_STRIDE];
    __shared__ __align__(16) __half Ws[64 * WS_STRIDE];
    int tid = threadIdx.x;
    int lane = tid & 31;
    int wid = tid >> 5;
    int warp_m = (wid >> 1) * 32;
    int warp_n = (wid & 1) * 32;
    int m0 = blockIdx.x * 128;
    int n0 = blockIdx.y * 64;
    int gid = lane >> 2;
    int tig = lane & 3;

    float acc[2][4][4];
#pragma unroll
    for (int i = 0; i < 2; i++)
#pragma unroll
        for (int j = 0; j < 4; j++)
#pragma unroll
            for (int c = 0; c < 4; c++) acc[i][j][c] = 0.f;

    for (int k0 = 0; k0 < K; k0 += 32) {
        {
            int r = tid >> 2;
            int c8 = (tid & 3) * 8;
#pragma unroll
            for (int p = 0; p < 2; p++) {
                int row = r + p * 64;
                uint4 v = *(const uint4*)&A[(size_t)(m0 + row) * K + k0 + c8];
                *(uint4*)&As[row * AS_STRIDE + c8] = v;
            }
        }
        {
            int wr = tid >> 4;
            int c4 = (tid & 15) * 4;
#pragma unroll
            for (int p = 0; p < 2; p++) {
                int k = wr + p * 16;
                float4 v = *(const float4*)&W[(size_t)(k0 + k) * N + n0 + c4];
                Ws[(c4 + 0) * WS_STRIDE + k] = __float2half(v.x);
                Ws[(c4 + 1) * WS_STRIDE + k] = __float2half(v.y);
                Ws[(c4 + 2) * WS_STRIDE + k] = __float2half(v.z);
                Ws[(c4 + 3) * WS_STRIDE + k] = __float2half(v.w);
            }
        }
        __syncthreads();
#pragma unroll
        for (int kk = 0; kk < 32; kk += 16) {
            uint32_t af[2][4];
#pragma unroll
            for (int mi = 0; mi < 2; mi++) {
                int mb = warp_m + mi * 16;
                const __half* a0 = &As[(mb + gid) * AS_STRIDE + kk + tig * 2];
                const __half* a1 = &As[(mb + gid + 8) * AS_STRIDE + kk + tig * 2];
                af[mi][0] = *(const uint32_t*)a0;
                af[mi][1] = *(const uint32_t*)a1;
                af[mi][2] = *(const uint32_t*)(a0 + 8);
                af[mi][3] = *(const uint32_t*)(a1 + 8);
            }
            uint32_t bf[4][2];
#pragma unroll
            for (int ni = 0; ni < 4; ni++) {
                int nb = warp_n + ni * 8;
                const __half* b0 = &Ws[(nb + gid) * WS_STRIDE + kk + tig * 2];
                bf[ni][0] = *(const uint32_t*)b0;
                bf[ni][1] = *(const uint32_t*)(b0 + 8);
            }
#pragma unroll
            for (int mi = 0; mi < 2; mi++)
#pragma unroll
                for (int ni = 0; ni < 4; ni++) {
                    asm volatile(
                        "mma.sync.aligned.m16n8k16.row.col.f32.f16.f16.f32 "
                        "{%0,%1,%2,%3}, {%4,%5,%6,%7}, {%8,%9}, {%0,%1,%2,%3};"
                        : "+f"(acc[mi][ni][0]), "+f"(acc[mi][ni][1]),
                          "+f"(acc[mi][ni][2]), "+f"(acc[mi][ni][3])
                        : "r"(af[mi][0]), "r"(af[mi][1]),
                          "r"(af[mi][2]), "r"(af[mi][3]),
                          "r"(bf[ni][0]), "r"(bf[ni][1]));
                }
        }
        __syncthreads();
    }
#pragma unroll
    for (int mi = 0; mi < 2; mi++) {
        int row0 = m0 + warp_m + mi * 16 + gid;
#pragma unroll
        for (int ni = 0; ni < 4; ni++) {
            int col = n0 + warp_n + ni * 8 + tig * 2;
            float b0 = bias[col], b1 = bias[col + 1];
            float2 o0 = make_float2(acc[mi][ni][0] + b0, acc[mi][ni][1] + b1);
            float2 o1 = make_float2(acc[mi][ni][2] + b0, acc[mi][ni][3] + b1);
            if (RELU) {
                o0.x = fmaxf(o0.x, 0.f); o0.y = fmaxf(o0.y, 0.f);
                o1.x = fmaxf(o1.x, 0.f); o1.y = fmaxf(o1.y, 0.f);
            }
            if (OUTHALF) {
                __half* C = (__half*)Cout;
                *(__half2*)&C[(size_t)row0 * N + col] = __floats2half2_rn(o0.x, o0.y);
                *(__half2*)&C[(size_t)(row0 + 8) * N + col] = __floats2half2_rn(o1.x, o1.y);
            } else {
                float* C = (float*)Cout;
                *(float2*)&C[(size_t)row0 * N + col] = o0;
                *(float2*)&C[(size_t)(row0 + 8) * N + col] = o1;
            }
        }
    }
}

// ---------------- x += LN(h); refresh fp16 mirror (per row, warp) ----------
__global__ __launch_bounds__(256) void k_ln_residual(const float* __restrict__ h,
                                                     const float* __restrict__ gam,
                                                     const float* __restrict__ bet) {
    int row = (blockIdx.x * 256 + threadIdx.x) >> 5;
    int lane = threadIdx.x & 31;
    float4 v = *(const float4*)&h[row * DD + lane * 4];
    float s = v.x + v.y + v.z + v.w;
#pragma unroll
    for (int o = 16; o; o >>= 1) s += __shfl_xor_sync(0xffffffffu, s, o);
    float mu = s * (1.f / 128.f);
    float dx = v.x - mu, dy = v.y - mu, dz = v.z - mu, dw = v.w - mu;
    float q = dx * dx + dy * dy + dz * dz + dw * dw;
#pragma unroll
    for (int o = 16; o; o >>= 1) q += __shfl_xor_sync(0xffffffffu, q, o);
    float rs = rsqrtf(q * (1.f / 128.f) + 1e-5f);
    float4 g4 = *(const float4*)&gam[lane * 4];
    float4 b4 = *(const float4*)&bet[lane * 4];
    float4 xo = *(const float4*)&g_x[row * DD + lane * 4];
    xo.x += dx * rs * g4.x + b4.x;
    xo.y += dy * rs * g4.y + b4.y;
    xo.z += dz * rs * g4.z + b4.z;
    xo.w += dw * rs * g4.w + b4.w;
    *(float4*)&g_x[row * DD + lane * 4] = xo;
    __half2 h0 = __floats2half2_rn(xo.x, xo.y);
    __half2 h1 = __floats2half2_rn(xo.z, xo.w);
    uint2 hv;
    hv.x = *(uint32_t*)&h0;
    hv.y = *(uint32_t*)&h1;
    *(uint2*)&g_xh[row * DD + lane * 4] = hv;
}

// ---------------- gate = relu(LN256(t)) . W2 + b2 (per row, warp) ----------
__global__ __launch_bounds__(256) void k_gate_finish(const float* __restrict__ gam,
                                                     const float* __restrict__ bet,
                                                     const float* __restrict__ w2,
                                                     const float* __restrict__ b2) {
    int row = (blockIdx.x * 256 + threadIdx.x) >> 5;
    int lane = threadIdx.x & 31;
    float4 v0 = *(const float4*)&g_t[row * HID + lane * 4];
    float4 v1 = *(const float4*)&g_t[row * HID + 128 + lane * 4];
    float s = v0.x + v0.y + v0.z + v0.w + v1.x + v1.y + v1.z + v1.w;
#pragma unroll
    for (int o = 16; o; o >>= 1) s += __shfl_xor_sync(0xffffffffu, s, o);
    float mu = s * (1.f / 256.f);
    float d0x = v0.x - mu, d0y = v0.y - mu, d0z = v0.z - mu, d0w = v0.w - mu;
    float d1x = v1.x - mu, d1y = v1.y - mu, d1z = v1.z - mu, d1w = v1.w - mu;
    float q = d0x * d0x + d0y * d0y + d0z * d0z + d0w * d0w +
              d1x * d1x + d1y * d1y + d1z * d1z + d1w * d1w;
#pragma unroll
    for (int o = 16; o; o >>= 1) q += __shfl_xor_sync(0xffffffffu, q, o);
    float rs = rsqrtf(q * (1.f / 256.f) + 1e-5f);
    float4 ga = *(const float4*)&gam[lane * 4];
    float4 gb = *(const float4*)&bet[lane * 4];
    float4 ga1 = *(const float4*)&gam[128 + lane * 4];
    float4 gb1 = *(const float4*)&bet[128 + lane * 4];
    float4 wa = *(const float4*)&w2[lane * 4];
    float4 wb = *(const float4*)&w2[128 + lane * 4];
    float dot =
        fmaxf(d0x * rs * ga.x + gb.x, 0.f) * wa.x +
        fmaxf(d0y * rs * ga.y + gb.y, 0.f) * wa.y +
        fmaxf(d0z * rs * ga.z + gb.z, 0.f) * wa.z +
        fmaxf(d0w * rs * ga.w + gb.w, 0.f) * wa.w +
        fmaxf(d1x * rs * ga1.x + gb1.x, 0.f) * wb.x +
        fmaxf(d1y * rs * ga1.y + gb1.y, 0.f) * wb.y +
        fmaxf(d1z * rs * ga1.z + gb1.z, 0.f) * wb.z +
        fmaxf(d1w * rs * ga1.w + gb1.w, 0.f) * wb.w;
#pragma unroll
    for (int o = 16; o; o >>= 1) dot += __shfl_xor_sync(0xffffffffu, dot, o);
    if (lane == 0) g_gate[row] = dot + b2[0];
}

// ---------------- tail: pool + 2 residual blocks + head (block per graph) --
__device__ __forceinline__ float block_ln(float v, float g, float bt, float* red) {
    int lane = threadIdx.x & 31, wid = threadIdx.x >> 5;
    float s = v;
#pragma unroll
    for (int o = 16; o; o >>= 1) s += __shfl_xor_sync(0xffffffffu, s, o);
    if (lane == 0) red[wid] = s;
    __syncthreads();
    float mu = (red[0] + red[1] + red[2] + red[3]) * (1.f / 128.f);
    float d = v - mu;
    float q = d * d;
#pragma unroll
    for (int o = 16; o; o >>= 1) q += __shfl_xor_sync(0xffffffffu, q, o);
    if (lane == 0) red[4 + wid] = q;
    __syncthreads();
    float var = (red[4] + red[5] + red[6] + red[7]) * (1.f / 128.f);
    float out = d * rsqrtf(var + 1e-5f) * g + bt;
    __syncthreads();
    return out;
}

__global__ __launch_bounds__(128) void k_tail(
    const float* __restrict__ fc1W, const float* __restrict__ fc1b,
    const float* __restrict__ ln1g, const float* __restrict__ ln1b,
    const float* __restrict__ fc2W, const float* __restrict__ fc2b,
    const float* __restrict__ ln2g, const float* __restrict__ ln2b,
    const float* __restrict__ pW1, const float* __restrict__ pb1,
    const float* __restrict__ pW2, const float* __restrict__ pb2,
    float* __restrict__ out) {
    __shared__ float sg[128], sh[128], red[8], w[64];
    int b = blockIdx.x, n = threadIdx.x;
    // ---- pool (segment softmax over the 64 nodes of graph b) ----
    if (n < 32) {
        float g0 = g_gate[b * 64 + n];
        float g1 = g_gate[b * 64 + 32 + n];
        float m = fmaxf(g0, g1);
#pragma unroll
        for (int o = 16; o; o >>= 1) m = fmaxf(m, __shfl_xor_sync(0xffffffffu, m, o));
        float e0 = expf(g0 - m), e1 = expf(g1 - m);
        float s = e0 + e1;
#pragma unroll
        for (int o = 16; o; o >>= 1) s += __shfl_xor_sync(0xffffffffu, s, o);
        w[n] = e0 / s;
        w[n + 32] = e1 / s;
    }
    __syncthreads();
    float pacc = 0.f;
#pragma unroll 8
    for (int i = 0; i < 64; i++) pacc += w[i] * g_x[(b * 64 + i) * DD + n];
    sg[n] = pacc;
    __syncthreads();
    // ---- 2 residual blocks ----
#pragma unroll
    for (int r = 0; r < 2; r++) {
        const float* W1 = fc1W + r * DD * DD;
        const float* W2 = fc2W + r * DD * DD;
        float u = fc1b[r * DD + n];
#pragma unroll 16
        for (int k = 0; k < 128; k++) u += sg[k] * W1[k * DD + n];
        float hn = gelu_erf(block_ln(u, ln1g[r * DD + n], ln1b[r * DD + n], red));
        sh[n] = hn;
        __syncthreads();
        float v2 = fc2b[r * DD + n];
#pragma unroll 16
        for (int k = 0; k < 128; k++) v2 += sh[k] * W2[k * DD + n];
        float h2 = block_ln(v2, ln2g[r * DD + n], ln2b[r * DD + n], red);
        sg[n] += h2;
        __syncthreads();
    }
    // ---- head ----
    float u = pb1[n];
#pragma unroll 16
    for (int k = 0; k < 128; k++) u += sg[k] * pW1[k * DD + n];
    sh[n] = gelu_erf(u);
    __syncthreads();
    if (n < 12) {
        float o = pb2[n];
#pragma unroll 16
        for (int k = 0; k < 128; k++) o += sh[k] * pW2[k * 12 + n];
        out[b * 12 + n] = o;
    }
}

// ---------------- launch ----------------
extern "C" void kernel_launch(void* const* d_in, const int* in_sizes, int n_in,
                              void* d_out, int out_size) {
    const float* logits   = (const float*)d_in[0];
    const int*   atom_feature = (const int*)d_in[2];
    const int*   edge_index   = (const int*)d_in[3];
    const int*   edge_attr    = (const int*)d_in[4];
    const float* atom_emb = (const float*)d_in[6];
    const float* edge_emb = (const float*)d_in[7];
    const float* gnn_W1 = (const float*)d_in[8];
    const float* gnn_b1 = (const float*)d_in[9];
    const float* gnn_W2 = (const float*)d_in[10];
    const float* gnn_b2 = (const float*)d_in[11];
    const float* gnn_ln_g = (const float*)d_in[12];
    const float* gnn_ln_b = (const float*)d_in[13];
    const float* gate_W1 = (const float*)d_in[14];
    const float* gate_b1 = (const float*)d_in[15];
    const float* gate_ln_g = (const float*)d_in[16];
    const float* gate_ln_b = (const float*)d_in[17];
    const float* gate_W2 = (const float*)d_in[18];
    const float* gate_b2 = (const float*)d_in[19];
    const float* res_fc1_W = (const float*)d_in[20];
    const float* res_fc1_b = (const float*)d_in[21];
    const float* res_ln1_g = (const float*)d_in[22];
    const float* res_ln1_b = (const float*)d_in[23];
    const float* res_fc2_W = (const float*)d_in[24];
    const float* res_fc2_b = (const float*)d_in[25];
    const float* res_ln2_g = (const float*)d_in[26];
    const float* res_ln2_b = (const float*)d_in[27];
    const float* pred_W1 = (const float*)d_in[28];
    const float* pred_b1 = (const float*)d_in[29];
    const float* pred_W2 = (const float*)d_in[30];
    const float* pred_b2 = (const float*)d_in[31];
    float* out = (float*)d_out;

    const int* e_src = edge_index;
    const int* e_dst = edge_index + NE;

    __half *agghp, *thp, *xhp;
    float *tp, *hp;
    cudaGetSymbolAddress((void**)&agghp, g_aggh);
    cudaGetSymbolAddress((void**)&thp, g_th);
    cudaGetSymbolAddress((void**)&xhp, g_xh);
    cudaGetSymbolAddress((void**)&tp, g_t);
    cudaGetSymbolAddress((void**)&hp, g_h);

    k_build_x<<<NN, 128>>>(logits, atom_feature, atom_emb);
    k_zero_counts<<<NN / 256, 256>>>();
    k_hist<<<NE / 512, 256>>>(e_dst);
    k_scan1<<<32, 1024>>>();
    k_scan2<<<1, 32>>>();
    k_scan3<<<32, 1024>>>();
    k_scatter<<<NE / 512, 256>>>(e_src, e_dst, edge_attr);

    for (int l = 0; l < 3; l++) {
        k_aggregate<<<NN / 8, 256>>>(edge_emb);
        k_hgemm<1, 1><<<dim3(NN / 128, HID / 64), 256>>>(
            agghp, gnn_W1 + l * DD * HID, gnn_b1 + l * HID, thp, DD, HID);
        k_hgemm<0, 0><<<dim3(NN / 128, DD / 64), 256>>>(
            thp, gnn_W2 + l * HID * DD, gnn_b2 + l * DD, hp, HID, DD);
        k_ln_residual<<<NN / 8, 256>>>(hp, gnn_ln_g + l * DD, gnn_ln_b + l * DD);
    }

    k_hgemm<0, 0><<<dim3(NN / 128, HID / 64), 256>>>(
        xhp, gate_W1, gate_b1, tp, DD, HID);
    k_gate_finish<<<NN / 8, 256>>>(gate_ln_g, gate_ln_b, gate_W2, gate_b2);
    k_tail<<<NB, 128>>>(res_fc1_W, res_fc1_b, res_ln1_g, res_ln1_b,
                        res_fc2_W, res_fc2_b, res_ln2_g, res_ln2_b,
                        pred_W1, pred_b1, pred_W2, pred_b2, out);
}